// round 3
// baseline (speedup 1.0000x reference)
#include <cuda_runtime.h>
#include <cuda_bf16.h>

// SiLU(x) = x * sigmoid(x), elementwise, n = 134217728 fp32.
// HBM-bound streaming kernel: 8 independent float4 loads per thread (MLP=8),
// non-temporal load/store hints (zero reuse), fully coalesced block tiles.

__device__ __forceinline__ float silu1(float x) {
    float s = 1.0f / (1.0f + __expf(-x));
    return x * s;
}

__device__ __forceinline__ float4 silu4(float4 v) {
    float4 r;
    r.x = silu1(v.x);
    r.y = silu1(v.y);
    r.z = silu1(v.z);
    r.w = silu1(v.w);
    return r;
}

// Each block handles a contiguous tile of 2048 float4s.
// Thread t loads offsets t + k*256 for k=0..7 -> 8 independent in-flight
// LDG.128 per thread, all coalesced within warps.
__global__ void __launch_bounds__(256) silu_vec4x8_kernel(
    const float4* __restrict__ in, float4* __restrict__ out, int n4)
{
    int base = blockIdx.x * 2048 + threadIdx.x;

    if (base + 7 * 256 < n4) {
        // fast path: all 8 in range (true for every full tile)
        float4 v[8];
        #pragma unroll
        for (int k = 0; k < 8; k++)
            v[k] = __ldcs(in + base + k * 256);
        #pragma unroll
        for (int k = 0; k < 8; k++)
            __stcs(out + base + k * 256, silu4(v[k]));
    } else {
        #pragma unroll
        for (int k = 0; k < 8; k++) {
            int i = base + k * 256;
            if (i < n4) __stcs(out + i, silu4(__ldcs(in + i)));
        }
    }
}

// Tail for n not divisible by 4 (not hit for this shape).
__global__ void silu_tail_kernel(const float* __restrict__ in,
                                 float* __restrict__ out, int start, int n)
{
    int i = start + blockIdx.x * blockDim.x + threadIdx.x;
    if (i < n) out[i] = silu1(in[i]);
}

extern "C" void kernel_launch(void* const* d_in, const int* in_sizes, int n_in,
                              void* d_out, int out_size)
{
    const float* x = (const float*)d_in[0];
    float* y = (float*)d_out;
    int n = in_sizes[0];

    int n4 = n / 4;
    if (n4 > 0) {
        int blocks = (n4 + 2047) / 2048;
        silu_vec4x8_kernel<<<blocks, 256>>>(
            (const float4*)x, (float4*)y, n4);
    }
    int rem = n - n4 * 4;
    if (rem > 0) {
        silu_tail_kernel<<<1, 256>>>(x, y, n4 * 4, n);
    }
}